// round 1
// baseline (speedup 1.0000x reference)
#include <cuda_runtime.h>
#include <math.h>

#define LEAK 0.2f

__device__ __forceinline__ float leaky_(float x) { return x >= 0.f ? x : LEAK * x; }
__device__ __forceinline__ float sigm_(float x) { return 1.f / (1.f + expf(-x)); }

// One block per batch element. Only timesteps 0..2 matter (output is out[:,2:3,:]).
__global__ __launch_bounds__(512, 1)
void lstm_t2_kernel(
    const float* __restrict__ data,                                  // (32,4096,11)
    const float* __restrict__ W_M1, const float* __restrict__ b_M1,  // (6,8),(8)
    const float* __restrict__ W_M2, const float* __restrict__ b_M2,  // (8,16),(16)
    const float* __restrict__ W_T1, const float* __restrict__ b_T1,  // (11,8),(8)
    const float* __restrict__ W_T2, const float* __restrict__ b_T2,  // (8,16),(16)
    const float* __restrict__ W_S1, const float* __restrict__ b_S1,  // (58,32),(32)
    const float* __restrict__ W_S2, const float* __restrict__ b_S2,  // (32,64),(64)
    const float* __restrict__ Wk,                                    // (124,512)
    const float* __restrict__ Wr,                                    // (128,512)
    const float* __restrict__ b_l,                                   // (512)
    const float* __restrict__ W_P1, const float* __restrict__ b_P1,  // (128,64),(64)
    const float* __restrict__ W_P2, const float* __restrict__ b_P2,  // (64,32),(32)
    const float* __restrict__ W_P3, const float* __restrict__ b_P3,  // (32,16),(16)
    const float* __restrict__ W_P4, const float* __restrict__ b_P4,  // (16,8),(8)
    const float* __restrict__ W_P5, const float* __restrict__ b_P5,  // (8,3),(3)
    float* __restrict__ out)                                         // 96 + 416 floats
{
    const int tid = threadIdx.x;
    const int b   = blockIdx.x;
    const int T = 4096, F = 11;

    __shared__ float xs[3][11];       // raw inputs, t=0..2
    __shared__ float M1s[3][8], T1s[3][8];
    __shared__ float s_in[3][58];     // [M16 | Tsk16 | Psk16 | Pa1 | env3 | body6]
    __shared__ float S1s[3][32];
    __shared__ float lin[3][124];     // [M16 | Tsk16 | Psk16 | Pa1 | S64 | x11]
    __shared__ float zx[3][512];
    __shared__ float zbuf[512];
    __shared__ float hS[128], cS[128];
    __shared__ float d1[64], d2[32], d3[16], d4[8], d5[3], probs[3];

    // ---- Load 3 timesteps of input; init LSTM state ----
    if (tid < 33) {
        int t = tid / 11, k = tid % 11;
        xs[t][k] = data[((size_t)b * T + t) * F + k];
    }
    if (tid >= 64 && tid < 192) { hS[tid - 64] = 0.f; cS[tid - 64] = 0.f; }
    __syncthreads();

    // ---- M1 (body -> 8) and T1 (x -> 8, abs) in parallel ----
    if (tid < 24) {
        int t = tid >> 3, j = tid & 7;
        float a = b_M1[j];
        #pragma unroll
        for (int d = 0; d < 6; d++) a += xs[t][4 + d] * W_M1[d * 8 + j];
        M1s[t][j] = leaky_(a);
    } else if (tid >= 32 && tid < 56) {
        int idx = tid - 32, t = idx >> 3, j = idx & 7;
        float a = b_T1[j];
        #pragma unroll
        for (int d = 0; d < 11; d++) a += xs[t][d] * W_T1[d * 8 + j];
        T1s[t][j] = fabsf(leaky_(a));
    }
    __syncthreads();

    // ---- M (8->16) -> s_in[0:16], Tsk (8->16,abs) -> s_in[16:32] ----
    if (tid < 48) {
        int t = tid >> 4, j = tid & 15;
        float a = b_M2[j];
        #pragma unroll
        for (int d = 0; d < 8; d++) a += M1s[t][d] * W_M2[d * 16 + j];
        s_in[t][j] = leaky_(a);
    } else if (tid >= 64 && tid < 112) {
        int idx = tid - 64, t = idx >> 4, j = idx & 15;
        float a = b_T2[j];
        #pragma unroll
        for (int d = 0; d < 8; d++) a += T1s[t][d] * W_T2[d * 16 + j];
        s_in[t][16 + j] = fabsf(leaky_(a));
    }
    __syncthreads();

    // ---- Psk, Pa, env, body into s_in ----
    if (tid < 48) {                      // Psk = log1p(Tsk)
        int t = tid >> 4, j = tid & 15;
        s_in[t][32 + j] = log1pf(s_in[t][16 + j]);
    } else if (tid >= 64 && tid < 67) {  // Pa = log1p(Ta)
        int t = tid - 64;
        s_in[t][48] = log1pf(xs[t][1]);
    } else if (tid >= 96 && tid < 105) { // env
        int idx = tid - 96, t = idx / 3, k = idx % 3;
        s_in[t][49 + k] = xs[t][1 + k];
    } else if (tid >= 128 && tid < 146) { // body
        int idx = tid - 128, t = idx / 6, k = idx % 6;
        s_in[t][52 + k] = xs[t][4 + k];
    }
    __syncthreads();

    // ---- S1: 58 -> 32 ----
    if (tid < 96) {
        int t = tid >> 5, j = tid & 31;
        float a = b_S1[j];
        #pragma unroll 2
        for (int d = 0; d < 58; d++) a += s_in[t][d] * W_S1[d * 32 + j];
        S1s[t][j] = leaky_(a);
    }
    __syncthreads();

    // ---- S: 32 -> 64 (into lin[49:113]); copy [0:49] and x[113:124] ----
    if (tid < 192) {
        int t = tid / 64, j = tid % 64;
        float a = b_S2[j];
        #pragma unroll 4
        for (int d = 0; d < 32; d++) a += S1s[t][d] * W_S2[d * 64 + j];
        lin[t][49 + j] = leaky_(a);
    } else if (tid >= 192 && tid < 339) {
        int idx = tid - 192, t = idx / 49, k = idx % 49;
        lin[t][k] = s_in[t][k];
    } else if (tid >= 352 && tid < 385) {
        int idx = tid - 352, t = idx / 11, k = idx % 11;
        lin[t][113 + k] = xs[t][k];
    }
    __syncthreads();

    // ---- zx[t] = lin[t] @ Wk + b_l  (each thread = one of 512 outputs, 3 t's) ----
    {
        float a0 = b_l[tid], a1 = a0, a2 = a0;
        const float* wp = Wk + tid;
        #pragma unroll 4
        for (int d = 0; d < 124; d++) {
            float w = wp[(size_t)d * 512];
            a0 += lin[0][d] * w;
            a1 += lin[1][d] * w;
            a2 += lin[2][d] * w;
        }
        zx[0][tid] = a0; zx[1][tid] = a1; zx[2][tid] = a2;
    }
    __syncthreads();

    // ---- LSTM recurrence, t = 0..2 (h=c=0 initially; skip Wr matvec at t=0) ----
    for (int t = 0; t < 3; t++) {
        float zz = zx[t][tid];
        if (t > 0) {
            const float* wp = Wr + tid;
            #pragma unroll 4
            for (int d = 0; d < 128; d++) zz += hS[d] * wp[(size_t)d * 512];
        }
        zbuf[tid] = zz;
        __syncthreads();
        if (tid < 128) {
            float zi = zbuf[tid], zf = zbuf[128 + tid];
            float zg = zbuf[256 + tid], zo = zbuf[384 + tid];
            float cc = sigm_(zf) * cS[tid] + sigm_(zi) * leaky_(zg);
            cS[tid] = cc;
            hS[tid] = sigm_(zo) * leaky_(cc);
        }
        __syncthreads();
    }

    // ---- Head MLP: 128->64->32->16->8->3, each layer leaky ----
    if (tid < 64) {
        float a = b_P1[tid];
        #pragma unroll 4
        for (int d = 0; d < 128; d++) a += hS[d] * W_P1[d * 64 + tid];
        d1[tid] = leaky_(a);
    }
    __syncthreads();
    if (tid < 32) {
        float a = b_P2[tid];
        #pragma unroll 4
        for (int d = 0; d < 64; d++) a += d1[d] * W_P2[d * 32 + tid];
        d2[tid] = leaky_(a);
    }
    __syncthreads();
    if (tid < 16) {
        float a = b_P3[tid];
        #pragma unroll 4
        for (int d = 0; d < 32; d++) a += d2[d] * W_P3[d * 16 + tid];
        d3[tid] = leaky_(a);
    }
    __syncthreads();
    if (tid < 8) {
        float a = b_P4[tid];
        #pragma unroll
        for (int d = 0; d < 16; d++) a += d3[d] * W_P4[d * 8 + tid];
        d4[tid] = leaky_(a);
    }
    __syncthreads();
    if (tid < 3) {
        float a = b_P5[tid];
        #pragma unroll
        for (int d = 0; d < 8; d++) a += d4[d] * W_P5[d * 3 + tid];
        d5[tid] = leaky_(a);
    }
    __syncthreads();
    if (tid == 0) {
        float m = fmaxf(d5[0], fmaxf(d5[1], d5[2]));
        float e0 = expf(d5[0] - m), e1 = expf(d5[1] - m), e2 = expf(d5[2] - m);
        float s = e0 + e1 + e2;
        probs[0] = e0 / s; probs[1] = e1 / s; probs[2] = e2 / s;
    }
    __syncthreads();

    // ---- Outputs: output (32,1,3) then x (32,1,13) = [data[b,2,1:11], probs] ----
    if (tid < 3) out[b * 3 + tid] = probs[tid];
    if (tid >= 32 && tid < 45) {
        int k = tid - 32;
        out[96 + b * 13 + k] = (k < 10) ? xs[2][1 + k] : probs[k - 10];
    }
}

extern "C" void kernel_launch(void* const* d_in, const int* in_sizes, int n_in,
                              void* d_out, int out_size) {
    const float* data = (const float*)d_in[0];
    const float* W_M1 = (const float*)d_in[1];  const float* b_M1 = (const float*)d_in[2];
    const float* W_M2 = (const float*)d_in[3];  const float* b_M2 = (const float*)d_in[4];
    const float* W_T1 = (const float*)d_in[5];  const float* b_T1 = (const float*)d_in[6];
    const float* W_T2 = (const float*)d_in[7];  const float* b_T2 = (const float*)d_in[8];
    const float* W_S1 = (const float*)d_in[9];  const float* b_S1 = (const float*)d_in[10];
    const float* W_S2 = (const float*)d_in[11]; const float* b_S2 = (const float*)d_in[12];
    const float* Wk   = (const float*)d_in[13];
    const float* Wr   = (const float*)d_in[14];
    const float* b_l  = (const float*)d_in[15];
    const float* W_P1 = (const float*)d_in[16]; const float* b_P1 = (const float*)d_in[17];
    const float* W_P2 = (const float*)d_in[18]; const float* b_P2 = (const float*)d_in[19];
    const float* W_P3 = (const float*)d_in[20]; const float* b_P3 = (const float*)d_in[21];
    const float* W_P4 = (const float*)d_in[22]; const float* b_P4 = (const float*)d_in[23];
    const float* W_P5 = (const float*)d_in[24]; const float* b_P5 = (const float*)d_in[25];
    float* out = (float*)d_out;

    lstm_t2_kernel<<<32, 512>>>(data,
        W_M1, b_M1, W_M2, b_M2, W_T1, b_T1, W_T2, b_T2,
        W_S1, b_S1, W_S2, b_S2, Wk, Wr, b_l,
        W_P1, b_P1, W_P2, b_P2, W_P3, b_P3, W_P4, b_P4, W_P5, b_P5,
        out);
}

// round 2
// speedup vs baseline: 1.8660x; 1.8660x over previous
#include <cuda_runtime.h>
#include <math.h>

#define LEAK 0.2f

__device__ __forceinline__ float leaky_(float x) { return x >= 0.f ? x : LEAK * x; }
__device__ __forceinline__ float sigm_(float x) { return 1.f / (1.f + expf(-x)); }

// Shared weight-arena offsets (floats)
#define OFF_WM1 0
#define OFF_BM1 48
#define OFF_WM2 56
#define OFF_BM2 184
#define OFF_WT1 200
#define OFF_BT1 288
#define OFF_WT2 296
#define OFF_BT2 424
#define OFF_WS1 440
#define OFF_BS1 2296
#define OFF_WS2 2328
#define OFF_BS2 4376
#define OFF_BL  4440
#define OFF_WP2 4952
#define OFF_BP2 7000
#define OFF_WP3 7032
#define OFF_BP3 7544
#define OFF_WP4 7560
#define OFF_BP4 7688
#define OFF_WP5 7696
#define OFF_BP5 7720
#define ARENA_SZ 7723  /* +3 for BP5 -> 7723 floats; round up */

// One block per batch element. Only timesteps 0..2 matter (output is out[:,2:3,:]).
__global__ __launch_bounds__(1024, 1)
void lstm_t2_kernel(
    const float* __restrict__ data,
    const float* __restrict__ W_M1, const float* __restrict__ b_M1,
    const float* __restrict__ W_M2, const float* __restrict__ b_M2,
    const float* __restrict__ W_T1, const float* __restrict__ b_T1,
    const float* __restrict__ W_T2, const float* __restrict__ b_T2,
    const float* __restrict__ W_S1, const float* __restrict__ b_S1,
    const float* __restrict__ W_S2, const float* __restrict__ b_S2,
    const float* __restrict__ Wk,                                    // (124,512)
    const float* __restrict__ Wr,                                    // (128,512)
    const float* __restrict__ b_l,                                   // (512)
    const float* __restrict__ W_P1, const float* __restrict__ b_P1,  // (128,64)
    const float* __restrict__ W_P2, const float* __restrict__ b_P2,
    const float* __restrict__ W_P3, const float* __restrict__ b_P3,
    const float* __restrict__ W_P4, const float* __restrict__ b_P4,
    const float* __restrict__ W_P5, const float* __restrict__ b_P5,
    float* __restrict__ out)
{
    const int tid = threadIdx.x;
    const int b   = blockIdx.x;
    const int T = 4096, F = 11;

    __shared__ float warr[ARENA_SZ + 1];
    __shared__ float xs[3][11];
    __shared__ float M1s[3][8], T1s[3][8];
    __shared__ float s_in[3][58];
    __shared__ float S1s[3][32];
    __shared__ float lin[3][124];
    __shared__ float4 zxv[3][128];   // zx, as float4
    __shared__ float4 zbufv[128];    // z for one timestep
    __shared__ float hS[128], cS[128];
    __shared__ float d1[64], d2[32], d3[16], d4[8], d5[3], probs[3];

    // ---- Phase 0: prefetch all small weights into smem, load inputs, init state ----
#define CPY(off, src, n) for (int i = tid; i < (n); i += 1024) warr[(off) + i] = (src)[i];
    CPY(OFF_WM1, W_M1, 48)   CPY(OFF_BM1, b_M1, 8)
    CPY(OFF_WM2, W_M2, 128)  CPY(OFF_BM2, b_M2, 16)
    CPY(OFF_WT1, W_T1, 88)   CPY(OFF_BT1, b_T1, 8)
    CPY(OFF_WT2, W_T2, 128)  CPY(OFF_BT2, b_T2, 16)
    CPY(OFF_WS1, W_S1, 1856) CPY(OFF_BS1, b_S1, 32)
    CPY(OFF_WS2, W_S2, 2048) CPY(OFF_BS2, b_S2, 64)
    CPY(OFF_BL,  b_l,  512)
    CPY(OFF_WP2, W_P2, 2048) CPY(OFF_BP2, b_P2, 32)
    CPY(OFF_WP3, W_P3, 512)  CPY(OFF_BP3, b_P3, 16)
    CPY(OFF_WP4, W_P4, 128)  CPY(OFF_BP4, b_P4, 8)
    CPY(OFF_WP5, W_P5, 24)   CPY(OFF_BP5, b_P5, 3)
#undef CPY
    if (tid < 33) {
        int t = tid / 11, k = tid % 11;
        xs[t][k] = data[((size_t)b * T + t) * F + k];
    }
    if (tid >= 64 && tid < 192) { hS[tid - 64] = 0.f; cS[tid - 64] = 0.f; }
    __syncthreads();

    // ---- M1 (body->8) and T1 (x->8, abs) ----
    if (tid < 24) {
        int t = tid >> 3, j = tid & 7;
        float a = warr[OFF_BM1 + j];
        #pragma unroll
        for (int d = 0; d < 6; d++) a += xs[t][4 + d] * warr[OFF_WM1 + d * 8 + j];
        M1s[t][j] = leaky_(a);
    } else if (tid >= 32 && tid < 56) {
        int idx = tid - 32, t = idx >> 3, j = idx & 7;
        float a = warr[OFF_BT1 + j];
        #pragma unroll
        for (int d = 0; d < 11; d++) a += xs[t][d] * warr[OFF_WT1 + d * 8 + j];
        T1s[t][j] = fabsf(leaky_(a));
    }
    __syncthreads();

    // ---- M (8->16), Tsk (8->16,abs) ----
    if (tid < 48) {
        int t = tid >> 4, j = tid & 15;
        float a = warr[OFF_BM2 + j];
        #pragma unroll
        for (int d = 0; d < 8; d++) a += M1s[t][d] * warr[OFF_WM2 + d * 16 + j];
        s_in[t][j] = leaky_(a);
    } else if (tid >= 64 && tid < 112) {
        int idx = tid - 64, t = idx >> 4, j = idx & 15;
        float a = warr[OFF_BT2 + j];
        #pragma unroll
        for (int d = 0; d < 8; d++) a += T1s[t][d] * warr[OFF_WT2 + d * 16 + j];
        s_in[t][16 + j] = fabsf(leaky_(a));
    }
    __syncthreads();

    // ---- Psk, Pa, env, body into s_in ----
    if (tid < 48) {
        int t = tid >> 4, j = tid & 15;
        s_in[t][32 + j] = log1pf(s_in[t][16 + j]);
    } else if (tid >= 64 && tid < 67) {
        int t = tid - 64;
        s_in[t][48] = log1pf(xs[t][1]);
    } else if (tid >= 96 && tid < 105) {
        int idx = tid - 96, t = idx / 3, k = idx % 3;
        s_in[t][49 + k] = xs[t][1 + k];
    } else if (tid >= 128 && tid < 146) {
        int idx = tid - 128, t = idx / 6, k = idx % 6;
        s_in[t][52 + k] = xs[t][4 + k];
    }
    __syncthreads();

    // ---- S1: 58 -> 32 (smem weights) ----
    if (tid < 96) {
        int t = tid >> 5, j = tid & 31;
        float a = warr[OFF_BS1 + j];
        #pragma unroll 2
        for (int d = 0; d < 58; d++) a += s_in[t][d] * warr[OFF_WS1 + d * 32 + j];
        S1s[t][j] = leaky_(a);
    }
    __syncthreads();

    // ---- S: 32 -> 64 into lin[49:113]; copy lin[0:49] and x into lin[113:124] ----
    if (tid < 192) {
        int t = tid / 64, j = tid % 64;
        float a = warr[OFF_BS2 + j];
        #pragma unroll 4
        for (int d = 0; d < 32; d++) a += S1s[t][d] * warr[OFF_WS2 + d * 64 + j];
        lin[t][49 + j] = leaky_(a);
    } else if (tid >= 192 && tid < 339) {
        int idx = tid - 192, t = idx / 49, k = idx % 49;
        lin[t][k] = s_in[t][k];
    } else if (tid >= 352 && tid < 385) {
        int idx = tid - 352, t = idx / 11, k = idx % 11;
        lin[t][113 + k] = xs[t][k];
    }
    __syncthreads();

    // ---- zx = lin @ Wk + b_l : warp-split float4 matvec ----
    // warp w owns columns [w*16, w*16+16). lane: jq = l&3 (4-col group), dc = l>>2 (row chunk).
    {
        const int w = tid >> 5, l = tid & 31;
        const int jq = l & 3, dc = l >> 2;
        const int j4 = w * 4 + jq;                 // float4 column index (0..127)
        const float4* Wk4 = (const float4*)Wk;     // row stride 128 float4
        float4 a0 = {0,0,0,0}, a1 = {0,0,0,0}, a2 = {0,0,0,0};
        #pragma unroll
        for (int dd = 0; dd < 16; dd++) {
            int d = dc * 16 + ((dd + dc) & 15);    // staggered to spread smem banks
            if (d < 124) {
                float4 wv = Wk4[d * 128 + j4];
                float l0 = lin[0][d], l1 = lin[1][d], l2 = lin[2][d];
                a0.x += l0 * wv.x; a0.y += l0 * wv.y; a0.z += l0 * wv.z; a0.w += l0 * wv.w;
                a1.x += l1 * wv.x; a1.y += l1 * wv.y; a1.z += l1 * wv.z; a1.w += l1 * wv.w;
                a2.x += l2 * wv.x; a2.y += l2 * wv.y; a2.z += l2 * wv.z; a2.w += l2 * wv.w;
            }
        }
        #pragma unroll
        for (int off = 16; off >= 4; off >>= 1) {
            a0.x += __shfl_down_sync(0xffffffffu, a0.x, off);
            a0.y += __shfl_down_sync(0xffffffffu, a0.y, off);
            a0.z += __shfl_down_sync(0xffffffffu, a0.z, off);
            a0.w += __shfl_down_sync(0xffffffffu, a0.w, off);
            a1.x += __shfl_down_sync(0xffffffffu, a1.x, off);
            a1.y += __shfl_down_sync(0xffffffffu, a1.y, off);
            a1.z += __shfl_down_sync(0xffffffffu, a1.z, off);
            a1.w += __shfl_down_sync(0xffffffffu, a1.w, off);
            a2.x += __shfl_down_sync(0xffffffffu, a2.x, off);
            a2.y += __shfl_down_sync(0xffffffffu, a2.y, off);
            a2.z += __shfl_down_sync(0xffffffffu, a2.z, off);
            a2.w += __shfl_down_sync(0xffffffffu, a2.w, off);
        }
        if (l < 4) {
            float4 bl = ((const float4*)(warr + OFF_BL))[w * 4 + l];
            float4 r0 = {a0.x + bl.x, a0.y + bl.y, a0.z + bl.z, a0.w + bl.w};
            float4 r1 = {a1.x + bl.x, a1.y + bl.y, a1.z + bl.z, a1.w + bl.w};
            float4 r2 = {a2.x + bl.x, a2.y + bl.y, a2.z + bl.z, a2.w + bl.w};
            zxv[0][w * 4 + l] = r0;
            zxv[1][w * 4 + l] = r1;
            zxv[2][w * 4 + l] = r2;
        }
    }
    __syncthreads();

    // ---- LSTM recurrence t = 0..2 ----
    const float* zxf  = (const float*)zxv;
    float* zbuf = (float*)zbufv;
    for (int t = 0; t < 3; t++) {
        if (t == 0) {
            if (tid < 128) zbufv[tid] = zxv[0][tid];
        } else {
            const int w = tid >> 5, l = tid & 31;
            const int jq = l & 3, dc = l >> 2;
            const int j4 = w * 4 + jq;
            const float4* Wr4 = (const float4*)Wr;
            float4 acc = {0,0,0,0};
            #pragma unroll
            for (int dd = 0; dd < 16; dd++) {
                int d = dc * 16 + ((dd + dc) & 15);
                float4 wv = Wr4[d * 128 + j4];
                float hv = hS[d];
                acc.x += hv * wv.x; acc.y += hv * wv.y;
                acc.z += hv * wv.z; acc.w += hv * wv.w;
            }
            #pragma unroll
            for (int off = 16; off >= 4; off >>= 1) {
                acc.x += __shfl_down_sync(0xffffffffu, acc.x, off);
                acc.y += __shfl_down_sync(0xffffffffu, acc.y, off);
                acc.z += __shfl_down_sync(0xffffffffu, acc.z, off);
                acc.w += __shfl_down_sync(0xffffffffu, acc.w, off);
            }
            if (l < 4) {
                float4 zz = zxv[t][w * 4 + l];
                zz.x += acc.x; zz.y += acc.y; zz.z += acc.z; zz.w += acc.w;
                zbufv[w * 4 + l] = zz;
            }
        }
        __syncthreads();
        if (tid < 128) {
            float zi = zbuf[tid], zf = zbuf[128 + tid];
            float zg = zbuf[256 + tid], zo = zbuf[384 + tid];
            float cc = sigm_(zf) * cS[tid] + sigm_(zi) * leaky_(zg);
            cS[tid] = cc;
            hS[tid] = sigm_(zo) * leaky_(cc);
        }
        __syncthreads();
    }

    // ---- Head P1: 128->64, warp-split float4 from global (warps 0..3) ----
    if (tid < 128) {
        const int w = tid >> 5, l = tid & 31;
        const int jq = l & 3, dc = l >> 2;
        const int j4 = w * 4 + jq;                 // 0..15 (64 cols = 16 float4)
        const float4* Wp1 = (const float4*)W_P1;   // row stride 16 float4
        float4 acc = {0,0,0,0};
        #pragma unroll
        for (int dd = 0; dd < 16; dd++) {
            int d = dc * 16 + ((dd + dc) & 15);
            float4 wv = Wp1[d * 16 + j4];
            float hv = hS[d];
            acc.x += hv * wv.x; acc.y += hv * wv.y;
            acc.z += hv * wv.z; acc.w += hv * wv.w;
        }
        #pragma unroll
        for (int off = 16; off >= 4; off >>= 1) {
            acc.x += __shfl_down_sync(0xffffffffu, acc.x, off);
            acc.y += __shfl_down_sync(0xffffffffu, acc.y, off);
            acc.z += __shfl_down_sync(0xffffffffu, acc.z, off);
            acc.w += __shfl_down_sync(0xffffffffu, acc.w, off);
        }
        if (l < 4) {
            int jb = (w * 4 + l) * 4;
            float4 bp = ((const float4*)b_P1)[w * 4 + l];
            d1[jb + 0] = leaky_(acc.x + bp.x);
            d1[jb + 1] = leaky_(acc.y + bp.y);
            d1[jb + 2] = leaky_(acc.z + bp.z);
            d1[jb + 3] = leaky_(acc.w + bp.w);
        }
    }
    __syncthreads();
    if (tid < 32) {
        float a = warr[OFF_BP2 + tid];
        #pragma unroll 8
        for (int d = 0; d < 64; d++) a += d1[d] * warr[OFF_WP2 + d * 32 + tid];
        d2[tid] = leaky_(a);
    }
    __syncthreads();
    if (tid < 16) {
        float a = warr[OFF_BP3 + tid];
        #pragma unroll 8
        for (int d = 0; d < 32; d++) a += d2[d] * warr[OFF_WP3 + d * 16 + tid];
        d3[tid] = leaky_(a);
    }
    __syncthreads();
    if (tid < 8) {
        float a = warr[OFF_BP4 + tid];
        #pragma unroll
        for (int d = 0; d < 16; d++) a += d3[d] * warr[OFF_WP4 + d * 8 + tid];
        d4[tid] = leaky_(a);
    }
    __syncthreads();
    if (tid < 3) {
        float a = warr[OFF_BP5 + tid];
        #pragma unroll
        for (int d = 0; d < 8; d++) a += d4[d] * warr[OFF_WP5 + d * 3 + tid];
        d5[tid] = leaky_(a);
    }
    __syncthreads();
    if (tid == 0) {
        float m = fmaxf(d5[0], fmaxf(d5[1], d5[2]));
        float e0 = expf(d5[0] - m), e1 = expf(d5[1] - m), e2 = expf(d5[2] - m);
        float s = e0 + e1 + e2;
        probs[0] = e0 / s; probs[1] = e1 / s; probs[2] = e2 / s;
    }
    __syncthreads();

    // ---- Outputs: output (32,1,3) then x (32,1,13) = [data[b,2,1:11], probs] ----
    if (tid < 3) out[b * 3 + tid] = probs[tid];
    if (tid >= 32 && tid < 45) {
        int k = tid - 32;
        out[96 + b * 13 + k] = (k < 10) ? xs[2][1 + k] : probs[k - 10];
    }
    (void)zxf;
}

extern "C" void kernel_launch(void* const* d_in, const int* in_sizes, int n_in,
                              void* d_out, int out_size) {
    const float* data = (const float*)d_in[0];
    const float* W_M1 = (const float*)d_in[1];  const float* b_M1 = (const float*)d_in[2];
    const float* W_M2 = (const float*)d_in[3];  const float* b_M2 = (const float*)d_in[4];
    const float* W_T1 = (const float*)d_in[5];  const float* b_T1 = (const float*)d_in[6];
    const float* W_T2 = (const float*)d_in[7];  const float* b_T2 = (const float*)d_in[8];
    const float* W_S1 = (const float*)d_in[9];  const float* b_S1 = (const float*)d_in[10];
    const float* W_S2 = (const float*)d_in[11]; const float* b_S2 = (const float*)d_in[12];
    const float* Wk   = (const float*)d_in[13];
    const float* Wr   = (const float*)d_in[14];
    const float* b_l  = (const float*)d_in[15];
    const float* W_P1 = (const float*)d_in[16]; const float* b_P1 = (const float*)d_in[17];
    const float* W_P2 = (const float*)d_in[18]; const float* b_P2 = (const float*)d_in[19];
    const float* W_P3 = (const float*)d_in[20]; const float* b_P3 = (const float*)d_in[21];
    const float* W_P4 = (const float*)d_in[22]; const float* b_P4 = (const float*)d_in[23];
    const float* W_P5 = (const float*)d_in[24]; const float* b_P5 = (const float*)d_in[25];
    float* out = (float*)d_out;

    lstm_t2_kernel<<<32, 1024>>>(data,
        W_M1, b_M1, W_M2, b_M2, W_T1, b_T1, W_T2, b_T2,
        W_S1, b_S1, W_S2, b_S2, Wk, Wr, b_l,
        W_P1, b_P1, W_P2, b_P2, W_P3, b_P3, W_P4, b_P4, W_P5, b_P5,
        out);
}

// round 3
// speedup vs baseline: 2.6195x; 1.4038x over previous
#include <cuda_runtime.h>
#include <math.h>

#define LEAK 0.2f

__device__ __forceinline__ float leaky_(float x) { return x >= 0.f ? x : LEAK * x; }
__device__ __forceinline__ float sigm_(float x) { return 1.f / (1.f + expf(-x)); }

// Shared weight-arena offsets (floats)
#define OFF_WM1 0
#define OFF_BM1 48
#define OFF_WM2 56
#define OFF_BM2 184
#define OFF_WT1 200
#define OFF_BT1 288
#define OFF_WT2 296
#define OFF_BT2 424
#define OFF_WS1 440
#define OFF_BS1 2296
#define OFF_WS2 2328
#define OFF_BS2 4376
#define OFF_WP2 4440
#define OFF_BP2 6488
#define OFF_WP3 6520
#define OFF_BP3 7032
#define OFF_WP4 7048
#define OFF_BP4 7176
#define OFF_WP5 7184
#define OFF_BP5 7208
#define ARENA_SZ 7212

struct SmemT {
    float  warr[ARENA_SZ];
    float4 WrS4[128 * 32];     // 64 KB: Wr column slice for this rank
    float4 red0[256], red1[256], red2[256];   // cross-warp partials
    float  zxs[3][128];        // zx for this rank's 128 columns (incl b_l)
    float  zbuf[128];
    float  hFull[128];         // full h, assembled via DSMEM each step
    float  xs[3][11];
    float  M1s[3][8], T1s[3][8];
    float  s_in[3][58];
    float  S1s[3][32];
    float  lin[3][124];
    float  d1[64], d2[32], d3[16], d4[8], d5[3], probs[3];
};

__device__ __forceinline__ unsigned smem_u32_(const void* p) {
    unsigned a;
    asm("{ .reg .u64 t; cvta.to.shared.u64 t, %1; cvt.u32.u64 %0, t; }" : "=r"(a) : "l"(p));
    return a;
}
__device__ __forceinline__ void st_cluster_f32_(unsigned laddr, unsigned rank, float v) {
    asm volatile("{ .reg .b32 r; mapa.shared::cluster.u32 r, %0, %1; st.shared::cluster.f32 [r], %2; }"
                 :: "r"(laddr), "r"(rank), "f"(v) : "memory");
}
#define CLUSTER_SYNC_() do { \
    asm volatile("barrier.cluster.arrive.aligned;" ::: "memory"); \
    asm volatile("barrier.cluster.wait.aligned;"   ::: "memory"); } while (0)

// 4 CTAs per batch element (cluster). Rank r owns h[32r..32r+32) and z-columns
// {s*128 + 32r .. +32 | s=0..3}. Only timesteps 0..2 matter (output = out[:,2:3,:]).
__global__ __launch_bounds__(256, 1) __cluster_dims__(4, 1, 1)
void lstm_t2_kernel(
    const float* __restrict__ data,
    const float* __restrict__ W_M1, const float* __restrict__ b_M1,
    const float* __restrict__ W_M2, const float* __restrict__ b_M2,
    const float* __restrict__ W_T1, const float* __restrict__ b_T1,
    const float* __restrict__ W_T2, const float* __restrict__ b_T2,
    const float* __restrict__ W_S1, const float* __restrict__ b_S1,
    const float* __restrict__ W_S2, const float* __restrict__ b_S2,
    const float* __restrict__ Wk,   // (124,512)
    const float* __restrict__ Wr,   // (128,512)
    const float* __restrict__ b_l,  // (512)
    const float* __restrict__ W_P1, const float* __restrict__ b_P1,
    const float* __restrict__ W_P2, const float* __restrict__ b_P2,
    const float* __restrict__ W_P3, const float* __restrict__ b_P3,
    const float* __restrict__ W_P4, const float* __restrict__ b_P4,
    const float* __restrict__ W_P5, const float* __restrict__ b_P5,
    float* __restrict__ out)
{
    extern __shared__ char smraw[];
    SmemT& S = *reinterpret_cast<SmemT*>(smraw);

    const int tid  = threadIdx.x;
    const int w    = tid >> 5, lane = tid & 31;
    const int b    = blockIdx.x >> 2;        // batch
    const int rank = blockIdx.x & 3;         // cluster rank
    const int T = 4096, F = 11;

    // column-group-of-4 (float4 units) this lane owns within [0,512):
    // strip = lane>>3 (i/f/g/o), w8 = lane&7
    const int gc4 = ((lane >> 3) * 32) + rank * 8 + (lane & 7);

    // ---- Stage Wr column slice into smem (used twice: t=1, t=2) ----
    {
        const float4* Wr4 = (const float4*)Wr;   // row stride 128 float4
        #pragma unroll 4
        for (int k = 0; k < 16; k++) {
            int d = w + 8 * k;                   // 0..127
            S.WrS4[d * 32 + lane] = Wr4[d * 128 + gc4];
        }
    }

    // ---- Prefetch small weights into smem arena (float4 where possible) ----
#define CPY4(off, src, n) { const float4* s4 = (const float4*)(src); float4* d4_ = (float4*)(S.warr + (off)); \
    for (int i = tid; i < (n) / 4; i += 256) d4_[i] = s4[i]; }
    CPY4(OFF_WM1, W_M1, 48)   CPY4(OFF_BM1, b_M1, 8)
    CPY4(OFF_WM2, W_M2, 128)  CPY4(OFF_BM2, b_M2, 16)
    CPY4(OFF_WT1, W_T1, 88)   CPY4(OFF_BT1, b_T1, 8)
    CPY4(OFF_WT2, W_T2, 128)  CPY4(OFF_BT2, b_T2, 16)
    CPY4(OFF_WS1, W_S1, 1856) CPY4(OFF_BS1, b_S1, 32)
    CPY4(OFF_WS2, W_S2, 2048) CPY4(OFF_BS2, b_S2, 64)
    if (rank == 0) {
        CPY4(OFF_WP2, W_P2, 2048) CPY4(OFF_BP2, b_P2, 32)
        CPY4(OFF_WP3, W_P3, 512)  CPY4(OFF_BP3, b_P3, 16)
        CPY4(OFF_WP4, W_P4, 128)  CPY4(OFF_BP4, b_P4, 8)
        CPY4(OFF_WP5, W_P5, 24)
        if (tid < 3) S.warr[OFF_BP5 + tid] = W_P5[24 + 0], S.warr[OFF_BP5 + tid] = b_P5[tid];
    }
#undef CPY4
    if (tid < 33) {
        int t = tid / 11, k = tid % 11;
        S.xs[t][k] = data[((size_t)b * T + t) * F + k];
    }
    __syncthreads();

    // ---- Prologue (duplicated per rank; tiny) ----
    if (tid < 24) {
        int t = tid >> 3, j = tid & 7;
        float a = S.warr[OFF_BM1 + j];
        #pragma unroll
        for (int d = 0; d < 6; d++) a += S.xs[t][4 + d] * S.warr[OFF_WM1 + d * 8 + j];
        S.M1s[t][j] = leaky_(a);
    } else if (tid >= 32 && tid < 56) {
        int idx = tid - 32, t = idx >> 3, j = idx & 7;
        float a = S.warr[OFF_BT1 + j];
        #pragma unroll
        for (int d = 0; d < 11; d++) a += S.xs[t][d] * S.warr[OFF_WT1 + d * 8 + j];
        S.T1s[t][j] = fabsf(leaky_(a));
    } else if (tid >= 64 && tid < 97) {       // x -> lin[113:124]
        int idx = tid - 64, t = idx / 11, k = idx % 11;
        S.lin[t][113 + k] = S.xs[t][k];
    }
    __syncthreads();

    if (tid < 48) {
        int t = tid >> 4, j = tid & 15;
        float a = S.warr[OFF_BM2 + j];
        #pragma unroll
        for (int d = 0; d < 8; d++) a += S.M1s[t][d] * S.warr[OFF_WM2 + d * 16 + j];
        S.s_in[t][j] = leaky_(a);
    } else if (tid >= 64 && tid < 112) {
        int idx = tid - 64, t = idx >> 4, j = idx & 15;
        float a = S.warr[OFF_BT2 + j];
        #pragma unroll
        for (int d = 0; d < 8; d++) a += S.T1s[t][d] * S.warr[OFF_WT2 + d * 16 + j];
        S.s_in[t][16 + j] = fabsf(leaky_(a));
    }
    __syncthreads();

    if (tid < 48) {
        int t = tid >> 4, j = tid & 15;
        S.s_in[t][32 + j] = log1pf(S.s_in[t][16 + j]);
    } else if (tid >= 64 && tid < 67) {
        int t = tid - 64;
        S.s_in[t][48] = log1pf(S.xs[t][1]);
    } else if (tid >= 96 && tid < 105) {
        int idx = tid - 96, t = idx / 3, k = idx % 3;
        S.s_in[t][49 + k] = S.xs[t][1 + k];
    } else if (tid >= 128 && tid < 146) {
        int idx = tid - 128, t = idx / 6, k = idx % 6;
        S.s_in[t][52 + k] = S.xs[t][4 + k];
    }
    __syncthreads();

    // S1: 58->32 ; also copy lin[t][0:49] = s_in[t][0:49]
    if (tid < 96) {
        int t = tid >> 5, j = tid & 31;
        float a = S.warr[OFF_BS1 + j];
        #pragma unroll 2
        for (int d = 0; d < 58; d++) a += S.s_in[t][d] * S.warr[OFF_WS1 + d * 32 + j];
        S.S1s[t][j] = leaky_(a);
    } else if (tid >= 128) {
        for (int i = tid - 128; i < 147; i += 128) {
            int t = i / 49, k = i % 49;
            S.lin[t][k] = S.s_in[t][k];
        }
    }
    __syncthreads();

    // S2: 32->64 into lin[49:113]
    if (tid < 192) {
        int t = tid / 64, j = tid % 64;
        float a = S.warr[OFF_BS2 + j];
        #pragma unroll 4
        for (int d = 0; d < 32; d++) a += S.S1s[t][d] * S.warr[OFF_WS2 + d * 64 + j];
        S.lin[t][49 + j] = leaky_(a);
    }
    __syncthreads();

    // ---- zx = lin @ Wk[:, Zr] + b_l[Zr] : warp-per-row, float4 columns ----
    {
        const float4* Wk4 = (const float4*)Wk;   // row stride 128 float4
        float4 a0 = {0,0,0,0}, a1 = {0,0,0,0}, a2 = {0,0,0,0};
        #pragma unroll
        for (int k = 0; k < 16; k++) {
            int d = w + 8 * k;
            if (d < 124) {
                float4 wv = Wk4[d * 128 + gc4];
                float l0 = S.lin[0][d], l1 = S.lin[1][d], l2 = S.lin[2][d];
                a0.x += l0 * wv.x; a0.y += l0 * wv.y; a0.z += l0 * wv.z; a0.w += l0 * wv.w;
                a1.x += l1 * wv.x; a1.y += l1 * wv.y; a1.z += l1 * wv.z; a1.w += l1 * wv.w;
                a2.x += l2 * wv.x; a2.y += l2 * wv.y; a2.z += l2 * wv.z; a2.w += l2 * wv.w;
            }
        }
        S.red0[w * 32 + lane] = a0;
        S.red1[w * 32 + lane] = a1;
        S.red2[w * 32 + lane] = a2;
    }
    __syncthreads();
    if (tid < 128) {
        const int c = tid;
        const float* r0 = (const float*)S.red0;
        const float* r1 = (const float*)S.red1;
        const float* r2 = (const float*)S.red2;
        float s0 = 0.f, s1 = 0.f, s2 = 0.f;
        #pragma unroll
        for (int ww = 0; ww < 8; ww++) {
            s0 += r0[ww * 128 + c]; s1 += r1[ww * 128 + c]; s2 += r2[ww * 128 + c];
        }
        int g = ((c >> 5) * 128) + rank * 32 + (c & 31);
        float bl = b_l[g];
        S.zxs[0][c] = s0 + bl; S.zxs[1][c] = s1 + bl; S.zxs[2][c] = s2 + bl;
    }
    __syncthreads();

    // ---- LSTM recurrence t=0..2 with DSMEM h-exchange ----
    float creg = 0.f;
    // t = 0 (no Wr term)
    if (tid < 32) {
        float zi = S.zxs[0][tid],      zf = S.zxs[0][32 + tid];
        float zg = S.zxs[0][64 + tid], zo = S.zxs[0][96 + tid];
        creg = sigm_(zf) * 0.f + sigm_(zi) * leaky_(zg);
        float hv = sigm_(zo) * leaky_(creg);
        unsigned laddr = smem_u32_(&S.hFull[rank * 32 + tid]);
        #pragma unroll
        for (unsigned p = 0; p < 4; p++) st_cluster_f32_(laddr, p, hv);
    }
    CLUSTER_SYNC_();

    #pragma unroll
    for (int t = 1; t <= 2; t++) {
        // z = zx[t] + hFull @ WrSlice
        {
            float4 acc = {0,0,0,0};
            #pragma unroll
            for (int k = 0; k < 16; k++) {
                int d = w + 8 * k;
                float4 wv = S.WrS4[d * 32 + lane];
                float hv = S.hFull[d];
                acc.x += hv * wv.x; acc.y += hv * wv.y;
                acc.z += hv * wv.z; acc.w += hv * wv.w;
            }
            S.red0[w * 32 + lane] = acc;
        }
        __syncthreads();
        if (tid < 128) {
            const float* r0 = (const float*)S.red0;
            float s0 = 0.f;
            #pragma unroll
            for (int ww = 0; ww < 8; ww++) s0 += r0[ww * 128 + tid];
            S.zbuf[tid] = S.zxs[t][tid] + s0;
        }
        __syncthreads();
        if (tid < 32) {
            float zi = S.zbuf[tid],      zf = S.zbuf[32 + tid];
            float zg = S.zbuf[64 + tid], zo = S.zbuf[96 + tid];
            creg = sigm_(zf) * creg + sigm_(zi) * leaky_(zg);
            float hv = sigm_(zo) * leaky_(creg);
            unsigned laddr = smem_u32_(&S.hFull[rank * 32 + tid]);
            #pragma unroll
            for (unsigned p = 0; p < 4; p++) st_cluster_f32_(laddr, p, hv);
        }
        CLUSTER_SYNC_();
    }

    // ---- Head MLP + softmax + output: rank 0 only ----
    if (rank == 0) {
        if (tid < 128) {   // P1: 128->64, warp-split float4 from global
            const int w4 = tid >> 5, l = tid & 31;
            const int jq = l & 3, dc = l >> 2;
            const int j4 = w4 * 4 + jq;
            const float4* Wp1 = (const float4*)W_P1;   // row stride 16 float4
            float4 acc = {0,0,0,0};
            #pragma unroll
            for (int dd = 0; dd < 16; dd++) {
                int d = dc * 16 + ((dd + dc) & 15);
                float4 wv = Wp1[d * 16 + j4];
                float hv = S.hFull[d];
                acc.x += hv * wv.x; acc.y += hv * wv.y;
                acc.z += hv * wv.z; acc.w += hv * wv.w;
            }
            #pragma unroll
            for (int off = 16; off >= 4; off >>= 1) {
                acc.x += __shfl_down_sync(0xffffffffu, acc.x, off);
                acc.y += __shfl_down_sync(0xffffffffu, acc.y, off);
                acc.z += __shfl_down_sync(0xffffffffu, acc.z, off);
                acc.w += __shfl_down_sync(0xffffffffu, acc.w, off);
            }
            if (l < 4) {
                int jb = (w4 * 4 + l) * 4;
                float4 bp = ((const float4*)b_P1)[w4 * 4 + l];
                S.d1[jb + 0] = leaky_(acc.x + bp.x);
                S.d1[jb + 1] = leaky_(acc.y + bp.y);
                S.d1[jb + 2] = leaky_(acc.z + bp.z);
                S.d1[jb + 3] = leaky_(acc.w + bp.w);
            }
        }
        __syncthreads();
        if (tid < 32) {
            float a = S.warr[OFF_BP2 + tid];
            #pragma unroll 8
            for (int d = 0; d < 64; d++) a += S.d1[d] * S.warr[OFF_WP2 + d * 32 + tid];
            S.d2[tid] = leaky_(a);
        }
        __syncthreads();
        if (tid < 16) {
            float a = S.warr[OFF_BP3 + tid];
            #pragma unroll 8
            for (int d = 0; d < 32; d++) a += S.d2[d] * S.warr[OFF_WP3 + d * 16 + tid];
            S.d3[tid] = leaky_(a);
        }
        __syncthreads();
        if (tid < 8) {
            float a = S.warr[OFF_BP4 + tid];
            #pragma unroll
            for (int d = 0; d < 16; d++) a += S.d3[d] * S.warr[OFF_WP4 + d * 8 + tid];
            S.d4[tid] = leaky_(a);
        }
        __syncthreads();
        if (tid < 3) {
            float a = S.warr[OFF_BP5 + tid];
            #pragma unroll
            for (int d = 0; d < 8; d++) a += S.d4[d] * S.warr[OFF_WP5 + d * 3 + tid];
            S.d5[tid] = leaky_(a);
        }
        __syncthreads();
        if (tid == 0) {
            float m = fmaxf(S.d5[0], fmaxf(S.d5[1], S.d5[2]));
            float e0 = expf(S.d5[0] - m), e1 = expf(S.d5[1] - m), e2 = expf(S.d5[2] - m);
            float s = e0 + e1 + e2;
            S.probs[0] = e0 / s; S.probs[1] = e1 / s; S.probs[2] = e2 / s;
        }
        __syncthreads();
        if (tid < 3) out[b * 3 + tid] = S.probs[tid];
        if (tid >= 32 && tid < 45) {
            int k = tid - 32;
            out[96 + b * 13 + k] = (k < 10) ? S.xs[2][1 + k] : S.probs[k - 10];
        }
    }
}

extern "C" void kernel_launch(void* const* d_in, const int* in_sizes, int n_in,
                              void* d_out, int out_size) {
    const float* data = (const float*)d_in[0];
    const float* W_M1 = (const float*)d_in[1];  const float* b_M1 = (const float*)d_in[2];
    const float* W_M2 = (const float*)d_in[3];  const float* b_M2 = (const float*)d_in[4];
    const float* W_T1 = (const float*)d_in[5];  const float* b_T1 = (const float*)d_in[6];
    const float* W_T2 = (const float*)d_in[7];  const float* b_T2 = (const float*)d_in[8];
    const float* W_S1 = (const float*)d_in[9];  const float* b_S1 = (const float*)d_in[10];
    const float* W_S2 = (const float*)d_in[11]; const float* b_S2 = (const float*)d_in[12];
    const float* Wk   = (const float*)d_in[13];
    const float* Wr   = (const float*)d_in[14];
    const float* b_l  = (const float*)d_in[15];
    const float* W_P1 = (const float*)d_in[16]; const float* b_P1 = (const float*)d_in[17];
    const float* W_P2 = (const float*)d_in[18]; const float* b_P2 = (const float*)d_in[19];
    const float* W_P3 = (const float*)d_in[20]; const float* b_P3 = (const float*)d_in[21];
    const float* W_P4 = (const float*)d_in[22]; const float* b_P4 = (const float*)d_in[23];
    const float* W_P5 = (const float*)d_in[24]; const float* b_P5 = (const float*)d_in[25];
    float* out = (float*)d_out;

    static int smem_set = 0;
    (void)smem_set;
    cudaFuncSetAttribute(lstm_t2_kernel,
                         cudaFuncAttributeMaxDynamicSharedMemorySize,
                         (int)sizeof(SmemT));

    lstm_t2_kernel<<<128, 256, sizeof(SmemT)>>>(data,
        W_M1, b_M1, W_M2, b_M2, W_T1, b_T1, W_T2, b_T2,
        W_S1, b_S1, W_S2, b_S2, Wk, Wr, b_l,
        W_P1, b_P1, W_P2, b_P2, W_P3, b_P3, W_P4, b_P4, W_P5, b_P5,
        out);
}